// round 15
// baseline (speedup 1.0000x reference)
#include <cuda_runtime.h>
#include <cuda_bf16.h>
#include <cstdint>

#define N_NODES 100000
#define N_EDGES 1600000
#define N_GRAPHS 512
#define NHID 128
#define NLAYER 3

typedef unsigned long long ull;

// ---------------- scratch (static device arrays; no allocation) -------------
__device__ __align__(16) float g_h[(size_t)N_NODES * NHID];    // ping
__device__ __align__(16) float g_h2[(size_t)N_NODES * NHID];   // pong
__device__ __align__(16) float g_pool[N_GRAPHS * NHID];
__device__ int g_idx64;
__device__ int g_deg[N_NODES];
__device__ int g_rowoff[N_NODES + 1];
__device__ int g_csr_src[N_EDGES];
__device__ int g_bsum[128];
// bf16 weights, plain row-major [layer][mat][part(hi,lo)][128*128]
__device__ __align__(16) unsigned short g_wb[12 * 16384];

// ---------------- generic helpers -------------------------------------------
__device__ __forceinline__ void red_add_v4(float* addr, float4 v) {
    asm volatile("red.global.add.v4.f32 [%0], {%1,%2,%3,%4};"
                 :: "l"(addr), "f"(v.x), "f"(v.y), "f"(v.z), "f"(v.w)
                 : "memory");
}
__device__ __forceinline__ int load_idx(const void* raw, int i, int idx64) {
    return idx64 ? (int)((const long long*)raw)[i] : ((const int*)raw)[i];
}
__device__ __forceinline__ uint32_t smem_u32(const void* p) {
    uint32_t a;
    asm("{ .reg .u64 t; cvta.to.shared.u64 t, %1; cvt.u32.u64 %0, t; }"
        : "=r"(a) : "l"(p));
    return a;
}
__device__ __forceinline__ unsigned pack_bf16(__nv_bfloat16 a, __nv_bfloat16 b) {
    return (unsigned)__bfloat16_as_ushort(a) | ((unsigned)__bfloat16_as_ushort(b) << 16);
}

// ---------------- mma.sync helpers (sm_80+ portable) -------------------------
__device__ __forceinline__ void ldm_x4(uint32_t r[4], uint32_t addr) {
    asm volatile("ldmatrix.sync.aligned.m8n8.x4.shared.b16 {%0,%1,%2,%3}, [%4];"
                 : "=r"(r[0]), "=r"(r[1]), "=r"(r[2]), "=r"(r[3]) : "r"(addr));
}
__device__ __forceinline__ void mma_bf16(float acc[4], const uint32_t a[4], const uint32_t b[2]) {
    asm volatile("mma.sync.aligned.m16n8k16.row.col.f32.bf16.bf16.f32 "
                 "{%0,%1,%2,%3}, {%4,%5,%6,%7}, {%8,%9}, {%0,%1,%2,%3};"
                 : "+f"(acc[0]), "+f"(acc[1]), "+f"(acc[2]), "+f"(acc[3])
                 : "r"(a[0]), "r"(a[1]), "r"(a[2]), "r"(a[3]),
                   "r"(b[0]), "r"(b[1]));
}

// ---------------- index-width detection --------------------------------------
__global__ void detect_kernel(const int* __restrict__ ei_raw) {
    if (threadIdx.x == 0) {
        int odd = 0;
        for (int i = 0; i < 64; i++) odd |= ei_raw[2 * i + 1];
        g_idx64 = (odd == 0) ? 1 : 0;
    }
}

// ---------------- CSR build ---------------------------------------------------
__global__ void deg_zero_kernel() {
    int i = blockIdx.x * blockDim.x + threadIdx.x;
    if (i < N_NODES) g_deg[i] = 0;
}
__global__ void hist_kernel(const void* __restrict__ ei_raw) {
    int e = blockIdx.x * blockDim.x + threadIdx.x;
    if (e < N_EDGES) atomicAdd(&g_deg[load_idx(ei_raw, N_EDGES + e, g_idx64)], 1);
}
__global__ void scan1_kernel() {
    __shared__ int wsum[32];
    int b = blockIdx.x, t = threadIdx.x;
    int gi = b * 1024 + t;
    int v = (gi < N_NODES) ? g_deg[gi] : 0;
    int lane = t & 31, w = t >> 5;
    int s = v;
#pragma unroll
    for (int o = 1; o < 32; o <<= 1) {
        int u = __shfl_up_sync(0xffffffffu, s, o);
        if (lane >= o) s += u;
    }
    if (lane == 31) wsum[w] = s;
    __syncthreads();
    if (w == 0) {
        int ws = wsum[lane];
#pragma unroll
        for (int o = 1; o < 32; o <<= 1) {
            int u = __shfl_up_sync(0xffffffffu, ws, o);
            if (lane >= o) ws += u;
        }
        wsum[lane] = ws;
    }
    __syncthreads();
    int excl = s - v + (w > 0 ? wsum[w - 1] : 0);
    if (gi < N_NODES) g_rowoff[gi] = excl;
    if (t == 1023) g_bsum[b] = excl + v;
}
__global__ void scan2_kernel(int nblocks) {
    if (threadIdx.x == 0) {
        int acc = 0;
        for (int i = 0; i < nblocks; i++) { int t = g_bsum[i]; g_bsum[i] = acc; acc += t; }
        g_rowoff[N_NODES] = N_EDGES;
    }
}
__global__ void scan3_kernel() {
    int i = blockIdx.x * blockDim.x + threadIdx.x;
    if (i < N_NODES) { g_rowoff[i] += g_bsum[i >> 10]; g_deg[i] = 0; }
}
__global__ void fill_kernel(const void* __restrict__ ei_raw) {
    int e = blockIdx.x * blockDim.x + threadIdx.x;
    if (e < N_EDGES) {
        int idx64 = g_idx64;
        int s = load_idx(ei_raw, e, idx64);
        int d = load_idx(ei_raw, N_EDGES + e, idx64);
        g_csr_src[g_rowoff[d] + atomicAdd(&g_deg[d], 1)] = s;
    }
}

// ---------------- weight conversion (fp32 -> plain bf16 hi/lo) ---------------
__global__ void wconv_kernel(const float* __restrict__ W1, const float* __restrict__ W2) {
    int l = blockIdx.x >> 1, m = blockIdx.x & 1;
    const float* W = (m == 0 ? W1 : W2) + l * NHID * NHID;
    unsigned short* hi = g_wb + (size_t)((l * 2 + m) * 2 + 0) * 16384;
    unsigned short* lo = g_wb + (size_t)((l * 2 + m) * 2 + 1) * 16384;
    for (int i = threadIdx.x; i < 16384; i += blockDim.x) {
        float v = W[i];
        __nv_bfloat16 h = __float2bfloat16_rn(v);
        __nv_bfloat16 lw = __float2bfloat16_rn(v - __bfloat162float(h));
        hi[i] = __bfloat16_as_ushort(h);
        lo[i] = __bfloat16_as_ushort(lw);
    }
}

// ---------------- fused GIN layer (persistent, phase-alternating) ------------
// 148 CTAs x 512 thr; each CTA loops over 64-row tiles (stride gridDim).
// Per tile: ALL 16 warps gather z = h + sum h[neigh] in fp32 registers
// (warp = 4 rows, lane = float4, neighbor loop ILP 4) and write bf16 hi/lo
// straight into the smem A tile; then ALL 16 warps run GEMM1 -> epilogue1 ->
// GEMM2 -> store, exactly as R12. Weights staged once per CTA.
#define TROW 272
#define WTILE_B (128 * TROW)            // 34816
#define ATILE_B (64 * TROW)             // 17408
#define SM_W1HI 0
#define SM_W1LO (1 * WTILE_B)
#define SM_W2HI (2 * WTILE_B)
#define SM_W2LO (3 * WTILE_B)
#define SM_AHI  (4 * WTILE_B)                 // 139264
#define SM_ALO  (4 * WTILE_B + ATILE_B)       // 156672
#define SM_B1   (SM_AHI + 2 * ATILE_B)        // 174080
#define SM_B2   (SM_B1 + 512)
#define LAYER_SMEM_BYTES (SM_B2 + 512 + 256)  // ~175 KB
#define LAYER_THREADS 512
#define NTILES ((N_NODES + 63) / 64)          // 1563

__device__ __forceinline__ void gemm64(uint32_t sbase, uint32_t whi, uint32_t wlo,
                                       int mg, int ng, int lane, float acc[4][4]) {
    const uint32_t a0 = sbase + (uint32_t)(mg * 16 + (lane & 15)) * TROW
                      + (((uint32_t)lane >> 4) << 4);
    const uint32_t wb0 = (uint32_t)(ng * 32 + ((lane >> 4) & 1) * 8 + (lane & 7)) * TROW
                       + ((((uint32_t)lane >> 3) & 1) << 4);
#pragma unroll
    for (int kk = 0; kk < 8; kk++) {
        const uint32_t ka = kk * 32;
        uint32_t ahi[4], alo[4];
        ldm_x4(ahi, a0 + SM_AHI + ka);
        ldm_x4(alo, a0 + SM_ALO + ka);
#pragma unroll
        for (int p = 0; p < 2; p++) {
            uint32_t wh[4], wl[4];
            const uint32_t ba = sbase + wb0 + (uint32_t)(p * 16) * TROW + ka;
            ldm_x4(wh, ba + whi);
            ldm_x4(wl, ba + wlo);
            mma_bf16(acc[2 * p],     ahi, wh);
            mma_bf16(acc[2 * p],     ahi, wl);
            mma_bf16(acc[2 * p],     alo, wh);
            mma_bf16(acc[2 * p + 1], ahi, wh + 2);
            mma_bf16(acc[2 * p + 1], ahi, wl + 2);
            mma_bf16(acc[2 * p + 1], alo, wh + 2);
        }
    }
}

__global__ __launch_bounds__(LAYER_THREADS, 1)
void gin_layer_kernel(const float* __restrict__ hin,
                      const unsigned short* __restrict__ wb,
                      const float* __restrict__ b1, const float* __restrict__ b2,
                      float* __restrict__ hout) {
    extern __shared__ char smem[];
    const uint32_t sbase = smem_u32(smem);
    const int tid = threadIdx.x;
    const int wid = tid >> 5;
    const int lane = tid & 31;
    const int mg = wid >> 2;          // 0..3 -> rows mg*16..+15
    const int ng = wid & 3;           // 0..3 -> cols ng*32..+31
    const int cpair = 2 * (lane & 3);
    float* b1s = (float*)(smem + SM_B1);
    float* b2s = (float*)(smem + SM_B2);

    // stage all 4 weight tiles once (pad 128->136 bf16 rows)
#pragma unroll
    for (int t = 0; t < 4; t++) {
        const uint4* src = (const uint4*)(wb + (size_t)t * 16384);
        char* dst = smem + t * WTILE_B;
        for (int i = tid; i < 2048; i += LAYER_THREADS) {
            int r = i >> 4, c8 = i & 15;
            *(uint4*)(dst + r * TROW + c8 * 16) = src[i];
        }
    }
    if (tid < 128) { b1s[tid] = b1[tid]; b2s[tid] = b2[tid]; }
    __syncthreads();

    for (int tile = blockIdx.x; tile < NTILES; tile += gridDim.x) {
        const int row0 = tile * 64;

        // ---- phase 1: gather (all 16 warps; warp = 4 rows, lane = float4) ----
#pragma unroll 1
        for (int j = 0; j < 4; j++) {
            const int nd = wid * 4 + j;
            const int row = row0 + nd;
            float4 a = make_float4(0.f, 0.f, 0.f, 0.f);
            if (row < N_NODES) {
                a = *((const float4*)(hin + (size_t)row * NHID) + lane);
                const int beg = g_rowoff[row], end = g_rowoff[row + 1];
                for (int i = beg; i < end; i += 32) {
                    const int cnt = min(32, end - i);
                    int s = (lane < cnt) ? g_csr_src[i + lane] : 0;
                    int q = 0;
                    for (; q + 4 <= cnt; q += 4) {
                        int s0 = __shfl_sync(0xffffffffu, s, q);
                        int s1 = __shfl_sync(0xffffffffu, s, q + 1);
                        int s2 = __shfl_sync(0xffffffffu, s, q + 2);
                        int s3 = __shfl_sync(0xffffffffu, s, q + 3);
                        float4 v0 = *((const float4*)(hin + (size_t)s0 * NHID) + lane);
                        float4 v1 = *((const float4*)(hin + (size_t)s1 * NHID) + lane);
                        float4 v2 = *((const float4*)(hin + (size_t)s2 * NHID) + lane);
                        float4 v3 = *((const float4*)(hin + (size_t)s3 * NHID) + lane);
                        a.x += v0.x + v1.x + v2.x + v3.x;
                        a.y += v0.y + v1.y + v2.y + v3.y;
                        a.z += v0.z + v1.z + v2.z + v3.z;
                        a.w += v0.w + v1.w + v2.w + v3.w;
                    }
                    for (; q < cnt; q++) {
                        int sj = __shfl_sync(0xffffffffu, s, q);
                        float4 v = *((const float4*)(hin + (size_t)sj * NHID) + lane);
                        a.x += v.x; a.y += v.y; a.z += v.z; a.w += v.w;
                    }
                }
            }
            __nv_bfloat16 h0 = __float2bfloat16_rn(a.x), h1 = __float2bfloat16_rn(a.y);
            __nv_bfloat16 h2 = __float2bfloat16_rn(a.z), h3 = __float2bfloat16_rn(a.w);
            uint2 hv = make_uint2(pack_bf16(h0, h1), pack_bf16(h2, h3));
            uint2 lv = make_uint2(
                pack_bf16(__float2bfloat16_rn(a.x - __bfloat162float(h0)),
                          __float2bfloat16_rn(a.y - __bfloat162float(h1))),
                pack_bf16(__float2bfloat16_rn(a.z - __bfloat162float(h2)),
                          __float2bfloat16_rn(a.w - __bfloat162float(h3))));
            *(uint2*)(smem + SM_AHI + nd * TROW + lane * 8) = hv;
            *(uint2*)(smem + SM_ALO + nd * TROW + lane * 8) = lv;
        }
        __syncthreads();   // A tiles ready

        float acc[4][4];

        // ---- GEMM1: t = relu(z @ W1^T + b1) ----
#pragma unroll
        for (int nt = 0; nt < 4; nt++) {
            int col = ng * 32 + (nt >> 1) * 16 + (nt & 1) * 8 + cpair;
            float bb0 = b1s[col], bb1 = b1s[col + 1];
            acc[nt][0] = bb0; acc[nt][1] = bb1;
            acc[nt][2] = bb0; acc[nt][3] = bb1;
        }
        gemm64(sbase, SM_W1HI, SM_W1LO, mg, ng, lane, acc);
        __syncthreads();   // all warps done reading A

        // epilogue1: relu + hi/lo re-split into A tiles
        {
            int rA = mg * 16 + (lane >> 2);
#pragma unroll
            for (int nt = 0; nt < 4; nt++) {
                int col = ng * 32 + (nt >> 1) * 16 + (nt & 1) * 8 + cpair;
                float v0 = fmaxf(acc[nt][0], 0.f), v1 = fmaxf(acc[nt][1], 0.f);
                float v2 = fmaxf(acc[nt][2], 0.f), v3 = fmaxf(acc[nt][3], 0.f);
                __nv_bfloat16 h0 = __float2bfloat16_rn(v0), h1 = __float2bfloat16_rn(v1);
                __nv_bfloat16 h2 = __float2bfloat16_rn(v2), h3 = __float2bfloat16_rn(v3);
                *(unsigned*)(smem + SM_AHI + rA * TROW + col * 2) = pack_bf16(h0, h1);
                *(unsigned*)(smem + SM_AHI + (rA + 8) * TROW + col * 2) = pack_bf16(h2, h3);
                *(unsigned*)(smem + SM_ALO + rA * TROW + col * 2) =
                    pack_bf16(__float2bfloat16_rn(v0 - __bfloat162float(h0)),
                              __float2bfloat16_rn(v1 - __bfloat162float(h1)));
                *(unsigned*)(smem + SM_ALO + (rA + 8) * TROW + col * 2) =
                    pack_bf16(__float2bfloat16_rn(v2 - __bfloat162float(h2)),
                              __float2bfloat16_rn(v3 - __bfloat162float(h3)));
            }
        }
        __syncthreads();

        // ---- GEMM2: out = relu(t @ W2^T + b2) ----
#pragma unroll
        for (int nt = 0; nt < 4; nt++) {
            int col = ng * 32 + (nt >> 1) * 16 + (nt & 1) * 8 + cpair;
            float bb0 = b2s[col], bb1 = b2s[col + 1];
            acc[nt][0] = bb0; acc[nt][1] = bb1;
            acc[nt][2] = bb0; acc[nt][3] = bb1;
        }
        gemm64(sbase, SM_W2HI, SM_W2LO, mg, ng, lane, acc);

        // epilogue2: relu + global store (float2 pairs)
        {
            int grA = row0 + mg * 16 + (lane >> 2);
            int grB = grA + 8;
#pragma unroll
            for (int nt = 0; nt < 4; nt++) {
                int col = ng * 32 + (nt >> 1) * 16 + (nt & 1) * 8 + cpair;
                if (grA < N_NODES)
                    *(float2*)(hout + (size_t)grA * NHID + col) =
                        make_float2(fmaxf(acc[nt][0], 0.f), fmaxf(acc[nt][1], 0.f));
                if (grB < N_NODES)
                    *(float2*)(hout + (size_t)grB * NHID + col) =
                        make_float2(fmaxf(acc[nt][2], 0.f), fmaxf(acc[nt][3], 0.f));
            }
        }
        __syncthreads();   // A reads done before next tile's gather overwrites
    }
}

// ---------------- pooling + log_softmax --------------------------------------
__global__ void pool_zero_kernel() {
    int i = blockIdx.x * blockDim.x + threadIdx.x;
    if (i < N_GRAPHS * NHID) g_pool[i] = 0.f;
}
__global__ void pool_kernel(const float* __restrict__ h,
                            const void* __restrict__ batch_raw) {
    int t = blockIdx.x * blockDim.x + threadIdx.x;
    int n = t >> 5;
    int c = (t & 31) << 2;
    int g = load_idx(batch_raw, n, g_idx64);
    float4 v = *(const float4*)(h + (size_t)n * NHID + c);
    red_add_v4(g_pool + g * NHID + c, v);
}
__global__ void lsm_kernel(float* __restrict__ out) {
    int r = blockIdx.x;
    int c = threadIdx.x;
    int w = c >> 5, lane = c & 31;
    __shared__ float smax[4], ssum[4];
    float v = g_pool[r * NHID + c];
    float m = v;
#pragma unroll
    for (int off = 16; off > 0; off >>= 1)
        m = fmaxf(m, __shfl_xor_sync(0xffffffffu, m, off));
    if (lane == 0) smax[w] = m;
    __syncthreads();
    m = fmaxf(fmaxf(smax[0], smax[1]), fmaxf(smax[2], smax[3]));
    float e = expf(v - m);
    float s = e;
#pragma unroll
    for (int off = 16; off > 0; off >>= 1)
        s += __shfl_xor_sync(0xffffffffu, s, off);
    if (lane == 0) ssum[w] = s;
    __syncthreads();
    s = ssum[0] + ssum[1] + ssum[2] + ssum[3];
    out[r * NHID + c] = (v - m) - logf(s);
}

// ---------------- launch -----------------------------------------------------
extern "C" void kernel_launch(void* const* d_in, const int* in_sizes, int n_in,
                              void* d_out, int out_size) {
    const float* x     = nullptr;
    const void*  ei    = nullptr;
    const void*  batch = nullptr;
    const float *W1 = nullptr, *b1 = nullptr, *W2 = nullptr, *b2 = nullptr;
    for (int i = 0; i < n_in; i++) {
        int sz = in_sizes[i];
        if (sz == N_NODES * NHID)            x = (const float*)d_in[i];
        else if (sz == 2 * N_EDGES)          ei = d_in[i];
        else if (sz == N_NODES)              batch = d_in[i];
        else if (sz == NLAYER * NHID * NHID) { if (!W1) W1 = (const float*)d_in[i]; else W2 = (const float*)d_in[i]; }
        else if (sz == NLAYER * NHID)        { if (!b1) b1 = (const float*)d_in[i]; else b2 = (const float*)d_in[i]; }
    }
    float* out = (float*)d_out;

    float *hp = nullptr, *h2p = nullptr;
    unsigned short* wb = nullptr;
    cudaGetSymbolAddress((void**)&hp, g_h);
    cudaGetSymbolAddress((void**)&h2p, g_h2);
    cudaGetSymbolAddress((void**)&wb, g_wb);

    cudaFuncSetAttribute(gin_layer_kernel, cudaFuncAttributeMaxDynamicSharedMemorySize, LAYER_SMEM_BYTES);

    const int scan_blocks = (N_NODES + 1023) / 1024;
    const int edge_blocks = (N_EDGES + 255) / 256;
    const int node_blocks = (N_NODES + 255) / 256;
    const int pool_blocks = (N_NODES * 32) / 256;

    detect_kernel<<<1, 32>>>((const int*)ei);
    deg_zero_kernel<<<node_blocks, 256>>>();
    hist_kernel<<<edge_blocks, 256>>>(ei);
    scan1_kernel<<<scan_blocks, 1024>>>();
    scan2_kernel<<<1, 128>>>(scan_blocks);
    scan3_kernel<<<node_blocks, 256>>>();
    fill_kernel<<<edge_blocks, 256>>>(ei);
    wconv_kernel<<<6, 256>>>(W1, W2);

    const float* hin = x;
    float* bufs[2] = { hp, h2p };
    for (int l = 0; l < NLAYER; l++) {
        float* ho = bufs[l & 1];
        gin_layer_kernel<<<148, LAYER_THREADS, LAYER_SMEM_BYTES>>>(
            hin, wb + (size_t)l * 4 * 16384, b1 + l * NHID, b2 + l * NHID, ho);
        hin = ho;
    }

    pool_zero_kernel<<<(N_GRAPHS * NHID + 255) / 256, 256>>>();
    pool_kernel<<<pool_blocks, 256>>>(hin, batch);
    lsm_kernel<<<N_GRAPHS, NHID>>>(out);
}

// round 16
// speedup vs baseline: 1.3262x; 1.3262x over previous
#include <cuda_runtime.h>
#include <cuda_bf16.h>
#include <cstdint>

#define N_NODES 100000
#define N_EDGES 1600000
#define N_GRAPHS 512
#define NHID 128
#define NLAYER 3

typedef unsigned long long ull;

// ---------------- scratch (static device arrays; no allocation) -------------
__device__ __align__(16) float g_z[(size_t)N_NODES * NHID];   // z = h + agg
__device__ __align__(16) float g_h[(size_t)N_NODES * NHID];   // layer out
__device__ __align__(16) float g_pool[N_GRAPHS * NHID];
__device__ int g_idx64;
__device__ int g_deg[N_NODES];
__device__ int g_rowoff[N_NODES + 1];
__device__ int g_csr_src[N_EDGES];
__device__ int g_bsum[128];
// bf16 weights, plain row-major [layer][mat][part(hi,lo)][128*128]
__device__ __align__(16) unsigned short g_wb[12 * 16384];

// ---------------- generic helpers -------------------------------------------
__device__ __forceinline__ void red_add_v4(float* addr, float4 v) {
    asm volatile("red.global.add.v4.f32 [%0], {%1,%2,%3,%4};"
                 :: "l"(addr), "f"(v.x), "f"(v.y), "f"(v.z), "f"(v.w)
                 : "memory");
}
__device__ __forceinline__ int load_idx(const void* raw, int i, int idx64) {
    return idx64 ? (int)((const long long*)raw)[i] : ((const int*)raw)[i];
}
__device__ __forceinline__ uint32_t smem_u32(const void* p) {
    uint32_t a;
    asm("{ .reg .u64 t; cvta.to.shared.u64 t, %1; cvt.u32.u64 %0, t; }"
        : "=r"(a) : "l"(p));
    return a;
}
__device__ __forceinline__ unsigned pack_bf16(__nv_bfloat16 a, __nv_bfloat16 b) {
    return (unsigned)__bfloat16_as_ushort(a) | ((unsigned)__bfloat16_as_ushort(b) << 16);
}

// ---------------- mma.sync helpers (sm_80+ portable) -------------------------
__device__ __forceinline__ void ldm_x4(uint32_t r[4], uint32_t addr) {
    asm volatile("ldmatrix.sync.aligned.m8n8.x4.shared.b16 {%0,%1,%2,%3}, [%4];"
                 : "=r"(r[0]), "=r"(r[1]), "=r"(r[2]), "=r"(r[3]) : "r"(addr));
}
__device__ __forceinline__ void mma_bf16(float acc[4], const uint32_t a[4], const uint32_t b[2]) {
    asm volatile("mma.sync.aligned.m16n8k16.row.col.f32.bf16.bf16.f32 "
                 "{%0,%1,%2,%3}, {%4,%5,%6,%7}, {%8,%9}, {%0,%1,%2,%3};"
                 : "+f"(acc[0]), "+f"(acc[1]), "+f"(acc[2]), "+f"(acc[3])
                 : "r"(a[0]), "r"(a[1]), "r"(a[2]), "r"(a[3]),
                   "r"(b[0]), "r"(b[1]));
}
__device__ __forceinline__ void cpasync16(uint32_t dst, const void* src) {
    asm volatile("cp.async.cg.shared.global [%0], [%1], 16;"
                 :: "r"(dst), "l"(src) : "memory");
}
#define CP_COMMIT() asm volatile("cp.async.commit_group;" ::: "memory")
#define CP_WAIT0()  asm volatile("cp.async.wait_group 0;" ::: "memory")

// ---------------- detect + degree zero (merged) -------------------------------
__global__ void detect_degzero_kernel(const int* __restrict__ ei_raw) {
    int i = blockIdx.x * blockDim.x + threadIdx.x;
    if (i < N_NODES) g_deg[i] = 0;
    if (blockIdx.x == 0 && threadIdx.x == 0) {
        int odd = 0;
        for (int k = 0; k < 64; k++) odd |= ei_raw[2 * k + 1];
        g_idx64 = (odd == 0) ? 1 : 0;
    }
}

// ---------------- CSR build ---------------------------------------------------
__global__ void hist_kernel(const void* __restrict__ ei_raw) {
    int e = blockIdx.x * blockDim.x + threadIdx.x;
    if (e < N_EDGES) atomicAdd(&g_deg[load_idx(ei_raw, N_EDGES + e, g_idx64)], 1);
}
__global__ void scan1_kernel() {
    __shared__ int wsum[32];
    int b = blockIdx.x, t = threadIdx.x;
    int gi = b * 1024 + t;
    int v = (gi < N_NODES) ? g_deg[gi] : 0;
    int lane = t & 31, w = t >> 5;
    int s = v;
#pragma unroll
    for (int o = 1; o < 32; o <<= 1) {
        int u = __shfl_up_sync(0xffffffffu, s, o);
        if (lane >= o) s += u;
    }
    if (lane == 31) wsum[w] = s;
    __syncthreads();
    if (w == 0) {
        int ws = wsum[lane];
#pragma unroll
        for (int o = 1; o < 32; o <<= 1) {
            int u = __shfl_up_sync(0xffffffffu, ws, o);
            if (lane >= o) ws += u;
        }
        wsum[lane] = ws;
    }
    __syncthreads();
    int excl = s - v + (w > 0 ? wsum[w - 1] : 0);
    if (gi < N_NODES) g_rowoff[gi] = excl;
    if (t == 1023) g_bsum[b] = excl + v;
}
__global__ void scan2_kernel(int nblocks) {
    if (threadIdx.x == 0) {
        int acc = 0;
        for (int i = 0; i < nblocks; i++) { int t = g_bsum[i]; g_bsum[i] = acc; acc += t; }
        g_rowoff[N_NODES] = N_EDGES;
    }
}
__global__ void scan3_kernel() {
    int i = blockIdx.x * blockDim.x + threadIdx.x;
    if (i < N_NODES) { g_rowoff[i] += g_bsum[i >> 10]; g_deg[i] = 0; }
}
__global__ void fill_kernel(const void* __restrict__ ei_raw) {
    int e = blockIdx.x * blockDim.x + threadIdx.x;
    if (e < N_EDGES) {
        int idx64 = g_idx64;
        int s = load_idx(ei_raw, e, idx64);
        int d = load_idx(ei_raw, N_EDGES + e, idx64);
        g_csr_src[g_rowoff[d] + atomicAdd(&g_deg[d], 1)] = s;
    }
}

// ---------------- aggregation: z = h + sum_{src in N(dst)} h[src] ------------
__global__ __launch_bounds__(256, 8)
void gin_agg_kernel(const float* __restrict__ h, float* __restrict__ z) {
    int gw = (blockIdx.x * blockDim.x + threadIdx.x) >> 5;
    if (gw >= N_NODES) return;
    int lane = threadIdx.x & 31;
    int c = lane << 2;
    float4 acc = *(const float4*)(h + (size_t)gw * NHID + c);
    int beg = g_rowoff[gw], end = g_rowoff[gw + 1];
    for (int i = beg; i < end; i += 32) {
        int cnt = min(32, end - i);
        int s = (lane < cnt) ? g_csr_src[i + lane] : 0;
        for (int j = 0; j < cnt; j++) {
            int sj = __shfl_sync(0xffffffffu, s, j);
            float4 v = *(const float4*)(h + (size_t)sj * NHID + c);
            acc.x += v.x; acc.y += v.y; acc.z += v.z; acc.w += v.w;
        }
    }
    *(float4*)(z + (size_t)gw * NHID + c) = acc;
}

// ---------------- weight conversion (fp32 -> plain bf16 hi/lo) ---------------
__global__ void wconv_kernel(const float* __restrict__ W1, const float* __restrict__ W2) {
    int l = blockIdx.x >> 1, m = blockIdx.x & 1;
    const float* W = (m == 0 ? W1 : W2) + l * NHID * NHID;
    unsigned short* hi = g_wb + (size_t)((l * 2 + m) * 2 + 0) * 16384;
    unsigned short* lo = g_wb + (size_t)((l * 2 + m) * 2 + 1) * 16384;
    for (int i = threadIdx.x; i < 16384; i += blockDim.x) {
        float v = W[i];
        __nv_bfloat16 h = __float2bfloat16_rn(v);
        __nv_bfloat16 lw = __float2bfloat16_rn(v - __bfloat162float(h));
        hi[i] = __bfloat16_as_ushort(h);
        lo[i] = __bfloat16_as_ushort(lw);
    }
}

// ---------------- persistent HMMA fused MLP ----------------------------------
// 148 CTAs x 512 thr; each CTA loops over 64-row tiles (stride gridDim).
// Weights staged ONCE per CTA; next tile's z prefetched via cp.async during
// the GEMMs. bf16 hi/lo split (3 mma chains). 16 warps, warp tile 16x32.
#define TROW 272
#define WTILE_B (128 * TROW)            // 34816 (weight tile, 128 rows)
#define ATILE_B (64 * TROW)             // 17408 (A tile, 64 rows)
#define SM_W1HI 0
#define SM_W1LO (1 * WTILE_B)
#define SM_W2HI (2 * WTILE_B)
#define SM_W2LO (3 * WTILE_B)
#define SM_AHI  (4 * WTILE_B)                     // 139264
#define SM_ALO  (4 * WTILE_B + ATILE_B)           // 156672
#define SM_ZRAW (4 * WTILE_B + 2 * ATILE_B)       // 174080 (64 rows x 512 B)
#define SM_B1   (SM_ZRAW + 32768)                 // 206848
#define SM_B2   (SM_B1 + 512)
#define MMA_SMEM_BYTES (SM_B2 + 512 + 256)        // ~208 KB
#define MLP_THREADS 512
#define NTILES ((N_NODES + 63) / 64)              // 1563

__device__ __forceinline__ void prefetch_z(uint32_t sbase, const float* __restrict__ z,
                                           int tile, int tid) {
    int row0 = tile * 64;
#pragma unroll
    for (int k = 0; k < 4; k++) {
        int i = tid + k * MLP_THREADS;            // 2048 chunks of 16 B
        int r = i >> 5, c16 = i & 31;
        int row = row0 + r;
        if (row < N_NODES)
            cpasync16(sbase + SM_ZRAW + (uint32_t)i * 16,
                      z + (size_t)row * NHID + c16 * 4);
    }
}

__device__ __forceinline__ void gemm64(uint32_t sbase, uint32_t whi, uint32_t wlo,
                                       int mg, int ng, int lane, float acc[4][4]) {
    const uint32_t a0 = sbase + (uint32_t)(mg * 16 + (lane & 15)) * TROW
                      + (((uint32_t)lane >> 4) << 4);
    const uint32_t wb0 = (uint32_t)(ng * 32 + ((lane >> 4) & 1) * 8 + (lane & 7)) * TROW
                       + ((((uint32_t)lane >> 3) & 1) << 4);
#pragma unroll
    for (int kk = 0; kk < 8; kk++) {
        const uint32_t ka = kk * 32;
        uint32_t ahi[4], alo[4];
        ldm_x4(ahi, a0 + SM_AHI + ka);
        ldm_x4(alo, a0 + SM_ALO + ka);
#pragma unroll
        for (int p = 0; p < 2; p++) {
            uint32_t wh[4], wl[4];
            const uint32_t ba = sbase + wb0 + (uint32_t)(p * 16) * TROW + ka;
            ldm_x4(wh, ba + whi);
            ldm_x4(wl, ba + wlo);
            mma_bf16(acc[2 * p],     ahi, wh);
            mma_bf16(acc[2 * p],     ahi, wl);
            mma_bf16(acc[2 * p],     alo, wh);
            mma_bf16(acc[2 * p + 1], ahi, wh + 2);
            mma_bf16(acc[2 * p + 1], ahi, wl + 2);
            mma_bf16(acc[2 * p + 1], alo, wh + 2);
        }
    }
}

__global__ __launch_bounds__(MLP_THREADS, 1)
void mlp_mma_kernel(const float* __restrict__ zin,
                    const unsigned short* __restrict__ wb,   // w1hi,w1lo,w2hi,w2lo
                    const float* __restrict__ b1, const float* __restrict__ b2,
                    float* __restrict__ hout) {
    extern __shared__ char smem[];
    const uint32_t sbase = smem_u32(smem);
    const int tid = threadIdx.x;
    const int wid = tid >> 5;
    const int lane = tid & 31;
    const int mg = wid >> 2;          // 0..3 -> rows mg*16..+15
    const int ng = wid & 3;           // 0..3 -> cols ng*32..+31
    const int cpair = 2 * (lane & 3);
    float* b1s = (float*)(smem + SM_B1);
    float* b2s = (float*)(smem + SM_B2);

    int tile = blockIdx.x;
    if (tile < NTILES) prefetch_z(sbase, zin, tile, tid);
    CP_COMMIT();

    // stage all 4 weight tiles once (pad 128->136 bf16 rows)
#pragma unroll
    for (int t = 0; t < 4; t++) {
        const uint4* src = (const uint4*)(wb + (size_t)t * 16384);
        char* dst = smem + t * WTILE_B;
        for (int i = tid; i < 2048; i += MLP_THREADS) {
            int r = i >> 4, c8 = i & 15;
            *(uint4*)(dst + r * TROW + c8 * 16) = src[i];
        }
    }
    if (tid < 128) { b1s[tid] = b1[tid]; b2s[tid] = b2[tid]; }
    __syncthreads();

    for (; tile < NTILES; tile += gridDim.x) {
        const int row0 = tile * 64;
        const int next = tile + gridDim.x;

        CP_WAIT0();
        __syncthreads();   // all threads' cp.async data visible

        // convert zraw -> A hi/lo tiles
        for (int i = tid; i < 4096; i += MLP_THREADS) {   // 64 rows x 64 col-pairs
            int r = i >> 6, cp = i & 63, col = cp * 2;
            float2 v = make_float2(0.f, 0.f);
            if (row0 + r < N_NODES)
                v = *(const float2*)(smem + SM_ZRAW + r * 512 + col * 4);
            __nv_bfloat16 h0 = __float2bfloat16_rn(v.x), h1 = __float2bfloat16_rn(v.y);
            *(unsigned*)(smem + SM_AHI + r * TROW + col * 2) = pack_bf16(h0, h1);
            *(unsigned*)(smem + SM_ALO + r * TROW + col * 2) =
                pack_bf16(__float2bfloat16_rn(v.x - __bfloat162float(h0)),
                          __float2bfloat16_rn(v.y - __bfloat162float(h1)));
        }
        __syncthreads();   // A ready; zraw free

        if (next < NTILES) prefetch_z(sbase, zin, next, tid);
        CP_COMMIT();

        float acc[4][4];

        // ---- GEMM1: t = relu(z @ W1^T + b1) ----
#pragma unroll
        for (int nt = 0; nt < 4; nt++) {
            int col = ng * 32 + (nt >> 1) * 16 + (nt & 1) * 8 + cpair;
            float bb0 = b1s[col], bb1 = b1s[col + 1];
            acc[nt][0] = bb0; acc[nt][1] = bb1;
            acc[nt][2] = bb0; acc[nt][3] = bb1;
        }
        gemm64(sbase, SM_W1HI, SM_W1LO, mg, ng, lane, acc);
        __syncthreads();   // all warps done reading A

        // epilogue1: relu + hi/lo re-split into A tiles
        {
            int rA = mg * 16 + (lane >> 2);
#pragma unroll
            for (int nt = 0; nt < 4; nt++) {
                int col = ng * 32 + (nt >> 1) * 16 + (nt & 1) * 8 + cpair;
                float v0 = fmaxf(acc[nt][0], 0.f), v1 = fmaxf(acc[nt][1], 0.f);
                float v2 = fmaxf(acc[nt][2], 0.f), v3 = fmaxf(acc[nt][3], 0.f);
                __nv_bfloat16 h0 = __float2bfloat16_rn(v0), h1 = __float2bfloat16_rn(v1);
                __nv_bfloat16 h2 = __float2bfloat16_rn(v2), h3 = __float2bfloat16_rn(v3);
                *(unsigned*)(smem + SM_AHI + rA * TROW + col * 2) = pack_bf16(h0, h1);
                *(unsigned*)(smem + SM_AHI + (rA + 8) * TROW + col * 2) = pack_bf16(h2, h3);
                *(unsigned*)(smem + SM_ALO + rA * TROW + col * 2) =
                    pack_bf16(__float2bfloat16_rn(v0 - __bfloat162float(h0)),
                              __float2bfloat16_rn(v1 - __bfloat162float(h1)));
                *(unsigned*)(smem + SM_ALO + (rA + 8) * TROW + col * 2) =
                    pack_bf16(__float2bfloat16_rn(v2 - __bfloat162float(h2)),
                              __float2bfloat16_rn(v3 - __bfloat162float(h3)));
            }
        }
        __syncthreads();

        // ---- GEMM2: out = relu(t @ W2^T + b2) ----
#pragma unroll
        for (int nt = 0; nt < 4; nt++) {
            int col = ng * 32 + (nt >> 1) * 16 + (nt & 1) * 8 + cpair;
            float bb0 = b2s[col], bb1 = b2s[col + 1];
            acc[nt][0] = bb0; acc[nt][1] = bb1;
            acc[nt][2] = bb0; acc[nt][3] = bb1;
        }
        gemm64(sbase, SM_W2HI, SM_W2LO, mg, ng, lane, acc);

        // epilogue2: relu + store (float2 pairs)
        {
            int grA = row0 + mg * 16 + (lane >> 2);
            int grB = grA + 8;
#pragma unroll
            for (int nt = 0; nt < 4; nt++) {
                int col = ng * 32 + (nt >> 1) * 16 + (nt & 1) * 8 + cpair;
                if (grA < N_NODES)
                    *(float2*)(hout + (size_t)grA * NHID + col) =
                        make_float2(fmaxf(acc[nt][0], 0.f), fmaxf(acc[nt][1], 0.f));
                if (grB < N_NODES)
                    *(float2*)(hout + (size_t)grB * NHID + col) =
                        make_float2(fmaxf(acc[nt][2], 0.f), fmaxf(acc[nt][3], 0.f));
            }
        }
        __syncthreads();   // A reads done before next convert overwrites
    }
}

// ---------------- pooling + log_softmax --------------------------------------
__global__ void pool_zero_kernel() {
    int i = blockIdx.x * blockDim.x + threadIdx.x;
    if (i < N_GRAPHS * NHID) g_pool[i] = 0.f;
}
__global__ void pool_kernel(const float* __restrict__ h,
                            const void* __restrict__ batch_raw) {
    int t = blockIdx.x * blockDim.x + threadIdx.x;
    int n = t >> 5;
    int c = (t & 31) << 2;
    int g = load_idx(batch_raw, n, g_idx64);
    float4 v = *(const float4*)(h + (size_t)n * NHID + c);
    red_add_v4(g_pool + g * NHID + c, v);
}
__global__ void lsm_kernel(float* __restrict__ out) {
    int r = blockIdx.x;
    int c = threadIdx.x;
    int w = c >> 5, lane = c & 31;
    __shared__ float smax[4], ssum[4];
    float v = g_pool[r * NHID + c];
    float m = v;
#pragma unroll
    for (int off = 16; off > 0; off >>= 1)
        m = fmaxf(m, __shfl_xor_sync(0xffffffffu, m, off));
    if (lane == 0) smax[w] = m;
    __syncthreads();
    m = fmaxf(fmaxf(smax[0], smax[1]), fmaxf(smax[2], smax[3]));
    float e = expf(v - m);
    float s = e;
#pragma unroll
    for (int off = 16; off > 0; off >>= 1)
        s += __shfl_xor_sync(0xffffffffu, s, off);
    if (lane == 0) ssum[w] = s;
    __syncthreads();
    s = ssum[0] + ssum[1] + ssum[2] + ssum[3];
    out[r * NHID + c] = (v - m) - logf(s);
}

// ---------------- launch -----------------------------------------------------
extern "C" void kernel_launch(void* const* d_in, const int* in_sizes, int n_in,
                              void* d_out, int out_size) {
    const float* x     = nullptr;
    const void*  ei    = nullptr;
    const void*  batch = nullptr;
    const float *W1 = nullptr, *b1 = nullptr, *W2 = nullptr, *b2 = nullptr;
    for (int i = 0; i < n_in; i++) {
        int sz = in_sizes[i];
        if (sz == N_NODES * NHID)            x = (const float*)d_in[i];
        else if (sz == 2 * N_EDGES)          ei = d_in[i];
        else if (sz == N_NODES)              batch = d_in[i];
        else if (sz == NLAYER * NHID * NHID) { if (!W1) W1 = (const float*)d_in[i]; else W2 = (const float*)d_in[i]; }
        else if (sz == NLAYER * NHID)        { if (!b1) b1 = (const float*)d_in[i]; else b2 = (const float*)d_in[i]; }
    }
    float* out = (float*)d_out;

    float *zp = nullptr, *hp = nullptr;
    unsigned short* wb = nullptr;
    cudaGetSymbolAddress((void**)&zp, g_z);
    cudaGetSymbolAddress((void**)&hp, g_h);
    cudaGetSymbolAddress((void**)&wb, g_wb);

    cudaFuncSetAttribute(mlp_mma_kernel, cudaFuncAttributeMaxDynamicSharedMemorySize, MMA_SMEM_BYTES);

    const int scan_blocks = (N_NODES + 1023) / 1024;
    const int edge_blocks = (N_EDGES + 255) / 256;
    const int node_blocks = (N_NODES + 255) / 256;
    const int agg_blocks  = (N_NODES * 32 + 255) / 256;
    const int pool_blocks = (N_NODES * 32) / 256;

    detect_degzero_kernel<<<node_blocks, 256>>>((const int*)ei);
    hist_kernel<<<edge_blocks, 256>>>(ei);
    scan1_kernel<<<scan_blocks, 1024>>>();
    scan2_kernel<<<1, 128>>>(scan_blocks);
    scan3_kernel<<<node_blocks, 256>>>();
    fill_kernel<<<edge_blocks, 256>>>(ei);
    wconv_kernel<<<6, 256>>>(W1, W2);

    const float* hin = x;
    for (int l = 0; l < NLAYER; l++) {
        gin_agg_kernel<<<agg_blocks, 256>>>(hin, zp);
        mlp_mma_kernel<<<148, MLP_THREADS, MMA_SMEM_BYTES>>>(
            zp, wb + (size_t)l * 4 * 16384, b1 + l * NHID, b2 + l * NHID, hp);
        hin = hp;
    }

    pool_zero_kernel<<<(N_GRAPHS * NHID + 255) / 256, 256>>>();
    pool_kernel<<<pool_blocks, 256>>>(hp, batch);
    lsm_kernel<<<N_GRAPHS, NHID>>>(out);
}

// round 17
// speedup vs baseline: 1.4603x; 1.1011x over previous
#include <cuda_runtime.h>
#include <cuda_bf16.h>
#include <cuda_fp16.h>
#include <cstdint>

#define N_NODES 100000
#define N_EDGES 1600000
#define N_GRAPHS 512
#define NHID 128
#define NLAYER 3

typedef unsigned long long ull;

// ---------------- scratch (static device arrays; no allocation) -------------
__device__ __align__(16) float  g_z[(size_t)N_NODES * NHID];    // z = h + agg (fp32)
__device__ __align__(16) __half g_hh[(size_t)N_NODES * NHID];   // h in fp16
__device__ __align__(16) float  g_pool[N_GRAPHS * NHID];
__device__ int g_idx64;
__device__ int g_deg[N_NODES];
__device__ int g_rowoff[N_NODES + 1];
__device__ int g_csr_src[N_EDGES];
__device__ int g_bsum[128];
// bf16 weights, plain row-major [layer][mat][part(hi,lo)][128*128]
__device__ __align__(16) unsigned short g_wb[12 * 16384];

// ---------------- generic helpers -------------------------------------------
__device__ __forceinline__ void red_add_v4(float* addr, float4 v) {
    asm volatile("red.global.add.v4.f32 [%0], {%1,%2,%3,%4};"
                 :: "l"(addr), "f"(v.x), "f"(v.y), "f"(v.z), "f"(v.w)
                 : "memory");
}
__device__ __forceinline__ int load_idx(const void* raw, int i, int idx64) {
    return idx64 ? (int)((const long long*)raw)[i] : ((const int*)raw)[i];
}
__device__ __forceinline__ uint32_t smem_u32(const void* p) {
    uint32_t a;
    asm("{ .reg .u64 t; cvta.to.shared.u64 t, %1; cvt.u32.u64 %0, t; }"
        : "=r"(a) : "l"(p));
    return a;
}
__device__ __forceinline__ unsigned pack_bf16(__nv_bfloat16 a, __nv_bfloat16 b) {
    return (unsigned)__bfloat16_as_ushort(a) | ((unsigned)__bfloat16_as_ushort(b) << 16);
}
// load 4 fp16 at ptr (8B aligned) and accumulate into float4
__device__ __forceinline__ void acc_h4(float4& a, const __half* p) {
    uint2 u = *(const uint2*)p;
    __half2 p0 = *(__half2*)&u.x, p1 = *(__half2*)&u.y;
    float2 f0 = __half22float2(p0), f1 = __half22float2(p1);
    a.x += f0.x; a.y += f0.y; a.z += f1.x; a.w += f1.y;
}

// ---------------- mma.sync helpers (sm_80+ portable) -------------------------
__device__ __forceinline__ void ldm_x4(uint32_t r[4], uint32_t addr) {
    asm volatile("ldmatrix.sync.aligned.m8n8.x4.shared.b16 {%0,%1,%2,%3}, [%4];"
                 : "=r"(r[0]), "=r"(r[1]), "=r"(r[2]), "=r"(r[3]) : "r"(addr));
}
__device__ __forceinline__ void mma_bf16(float acc[4], const uint32_t a[4], const uint32_t b[2]) {
    asm volatile("mma.sync.aligned.m16n8k16.row.col.f32.bf16.bf16.f32 "
                 "{%0,%1,%2,%3}, {%4,%5,%6,%7}, {%8,%9}, {%0,%1,%2,%3};"
                 : "+f"(acc[0]), "+f"(acc[1]), "+f"(acc[2]), "+f"(acc[3])
                 : "r"(a[0]), "r"(a[1]), "r"(a[2]), "r"(a[3]),
                   "r"(b[0]), "r"(b[1]));
}
__device__ __forceinline__ void cpasync16(uint32_t dst, const void* src) {
    asm volatile("cp.async.cg.shared.global [%0], [%1], 16;"
                 :: "r"(dst), "l"(src) : "memory");
}
#define CP_COMMIT() asm volatile("cp.async.commit_group;" ::: "memory")
#define CP_WAIT0()  asm volatile("cp.async.wait_group 0;" ::: "memory")

// ---------------- detect + degree zero (merged) -------------------------------
__global__ void detect_degzero_kernel(const int* __restrict__ ei_raw) {
    int i = blockIdx.x * blockDim.x + threadIdx.x;
    if (i < N_NODES) g_deg[i] = 0;
    if (blockIdx.x == 0 && threadIdx.x == 0) {
        int odd = 0;
        for (int k = 0; k < 64; k++) odd |= ei_raw[2 * k + 1];
        g_idx64 = (odd == 0) ? 1 : 0;
    }
}

// ---------------- x -> fp16 conversion ----------------------------------------
__global__ void x16_kernel(const float4* __restrict__ x4, int n4) {
    int i = blockIdx.x * blockDim.x + threadIdx.x;
    if (i < n4) {
        float4 v = x4[i];
        __half2 h0 = __floats2half2_rn(v.x, v.y);
        __half2 h1 = __floats2half2_rn(v.z, v.w);
        ((uint2*)g_hh)[i] = make_uint2(*(unsigned*)&h0, *(unsigned*)&h1);
    }
}

// ---------------- CSR build ---------------------------------------------------
__global__ void hist_kernel(const void* __restrict__ ei_raw) {
    int e = blockIdx.x * blockDim.x + threadIdx.x;
    if (e < N_EDGES) atomicAdd(&g_deg[load_idx(ei_raw, N_EDGES + e, g_idx64)], 1);
}
__global__ void scan1_kernel() {
    __shared__ int wsum[32];
    int b = blockIdx.x, t = threadIdx.x;
    int gi = b * 1024 + t;
    int v = (gi < N_NODES) ? g_deg[gi] : 0;
    int lane = t & 31, w = t >> 5;
    int s = v;
#pragma unroll
    for (int o = 1; o < 32; o <<= 1) {
        int u = __shfl_up_sync(0xffffffffu, s, o);
        if (lane >= o) s += u;
    }
    if (lane == 31) wsum[w] = s;
    __syncthreads();
    if (w == 0) {
        int ws = wsum[lane];
#pragma unroll
        for (int o = 1; o < 32; o <<= 1) {
            int u = __shfl_up_sync(0xffffffffu, ws, o);
            if (lane >= o) ws += u;
        }
        wsum[lane] = ws;
    }
    __syncthreads();
    int excl = s - v + (w > 0 ? wsum[w - 1] : 0);
    if (gi < N_NODES) g_rowoff[gi] = excl;
    if (t == 1023) g_bsum[b] = excl + v;
}
__global__ void scan2_kernel(int nblocks) {
    if (threadIdx.x == 0) {
        int acc = 0;
        for (int i = 0; i < nblocks; i++) { int t = g_bsum[i]; g_bsum[i] = acc; acc += t; }
        g_rowoff[N_NODES] = N_EDGES;
    }
}
__global__ void scan3_kernel() {
    int i = blockIdx.x * blockDim.x + threadIdx.x;
    if (i < N_NODES) { g_rowoff[i] += g_bsum[i >> 10]; g_deg[i] = 0; }
}
__global__ void fill_kernel(const void* __restrict__ ei_raw) {
    int e = blockIdx.x * blockDim.x + threadIdx.x;
    if (e < N_EDGES) {
        int idx64 = g_idx64;
        int s = load_idx(ei_raw, e, idx64);
        int d = load_idx(ei_raw, N_EDGES + e, idx64);
        g_csr_src[g_rowoff[d] + atomicAdd(&g_deg[d], 1)] = s;
    }
}

// ---------------- aggregation: z = h + sum_{src in N(dst)} h[src], h fp16 ----
__global__ __launch_bounds__(256, 8)
void gin_agg_kernel(const __half* __restrict__ h, float* __restrict__ z) {
    int gw = (blockIdx.x * blockDim.x + threadIdx.x) >> 5;
    if (gw >= N_NODES) return;
    int lane = threadIdx.x & 31;
    int c = lane << 2;
    float4 acc = make_float4(0.f, 0.f, 0.f, 0.f);
    acc_h4(acc, h + (size_t)gw * NHID + c);
    int beg = g_rowoff[gw], end = g_rowoff[gw + 1];
    for (int i = beg; i < end; i += 32) {
        int cnt = min(32, end - i);
        int s = (lane < cnt) ? g_csr_src[i + lane] : 0;
        for (int j = 0; j < cnt; j++) {
            int sj = __shfl_sync(0xffffffffu, s, j);
            acc_h4(acc, h + (size_t)sj * NHID + c);
        }
    }
    *(float4*)(z + (size_t)gw * NHID + c) = acc;
}

// ---------------- weight conversion (fp32 -> plain bf16 hi/lo) ---------------
__global__ void wconv_kernel(const float* __restrict__ W1, const float* __restrict__ W2) {
    int l = blockIdx.x >> 1, m = blockIdx.x & 1;
    const float* W = (m == 0 ? W1 : W2) + l * NHID * NHID;
    unsigned short* hi = g_wb + (size_t)((l * 2 + m) * 2 + 0) * 16384;
    unsigned short* lo = g_wb + (size_t)((l * 2 + m) * 2 + 1) * 16384;
    for (int i = threadIdx.x; i < 16384; i += blockDim.x) {
        float v = W[i];
        __nv_bfloat16 h = __float2bfloat16_rn(v);
        __nv_bfloat16 lw = __float2bfloat16_rn(v - __bfloat162float(h));
        hi[i] = __bfloat16_as_ushort(h);
        lo[i] = __bfloat16_as_ushort(lw);
    }
}

// ---------------- persistent HMMA fused MLP ----------------------------------
// 148 CTAs x 512 thr; each CTA loops over 64-row tiles (stride gridDim).
// Weights staged ONCE per CTA; next tile's z prefetched via cp.async during
// the GEMMs. bf16 hi/lo split (3 mma chains). 16 warps, warp tile 16x32.
// Output h stored as fp16.
#define TROW 272
#define WTILE_B (128 * TROW)            // 34816 (weight tile, 128 rows)
#define ATILE_B (64 * TROW)             // 17408 (A tile, 64 rows)
#define SM_W1HI 0
#define SM_W1LO (1 * WTILE_B)
#define SM_W2HI (2 * WTILE_B)
#define SM_W2LO (3 * WTILE_B)
#define SM_AHI  (4 * WTILE_B)                     // 139264
#define SM_ALO  (4 * WTILE_B + ATILE_B)           // 156672
#define SM_ZRAW (4 * WTILE_B + 2 * ATILE_B)       // 174080 (64 rows x 512 B)
#define SM_B1   (SM_ZRAW + 32768)                 // 206848
#define SM_B2   (SM_B1 + 512)
#define MMA_SMEM_BYTES (SM_B2 + 512 + 256)        // ~208 KB
#define MLP_THREADS 512
#define NTILES ((N_NODES + 63) / 64)              // 1563

__device__ __forceinline__ void prefetch_z(uint32_t sbase, const float* __restrict__ z,
                                           int tile, int tid) {
    int row0 = tile * 64;
#pragma unroll
    for (int k = 0; k < 4; k++) {
        int i = tid + k * MLP_THREADS;            // 2048 chunks of 16 B
        int r = i >> 5, c16 = i & 31;
        int row = row0 + r;
        if (row < N_NODES)
            cpasync16(sbase + SM_ZRAW + (uint32_t)i * 16,
                      z + (size_t)row * NHID + c16 * 4);
    }
}

__device__ __forceinline__ void gemm64(uint32_t sbase, uint32_t whi, uint32_t wlo,
                                       int mg, int ng, int lane, float acc[4][4]) {
    const uint32_t a0 = sbase + (uint32_t)(mg * 16 + (lane & 15)) * TROW
                      + (((uint32_t)lane >> 4) << 4);
    const uint32_t wb0 = (uint32_t)(ng * 32 + ((lane >> 4) & 1) * 8 + (lane & 7)) * TROW
                       + ((((uint32_t)lane >> 3) & 1) << 4);
#pragma unroll
    for (int kk = 0; kk < 8; kk++) {
        const uint32_t ka = kk * 32;
        uint32_t ahi[4], alo[4];
        ldm_x4(ahi, a0 + SM_AHI + ka);
        ldm_x4(alo, a0 + SM_ALO + ka);
#pragma unroll
        for (int p = 0; p < 2; p++) {
            uint32_t wh[4], wl[4];
            const uint32_t ba = sbase + wb0 + (uint32_t)(p * 16) * TROW + ka;
            ldm_x4(wh, ba + whi);
            ldm_x4(wl, ba + wlo);
            mma_bf16(acc[2 * p],     ahi, wh);
            mma_bf16(acc[2 * p],     ahi, wl);
            mma_bf16(acc[2 * p],     alo, wh);
            mma_bf16(acc[2 * p + 1], ahi, wh + 2);
            mma_bf16(acc[2 * p + 1], ahi, wl + 2);
            mma_bf16(acc[2 * p + 1], alo, wh + 2);
        }
    }
}

__global__ __launch_bounds__(MLP_THREADS, 1)
void mlp_mma_kernel(const float* __restrict__ zin,
                    const unsigned short* __restrict__ wb,   // w1hi,w1lo,w2hi,w2lo
                    const float* __restrict__ b1, const float* __restrict__ b2,
                    __half* __restrict__ hout) {
    extern __shared__ char smem[];
    const uint32_t sbase = smem_u32(smem);
    const int tid = threadIdx.x;
    const int wid = tid >> 5;
    const int lane = tid & 31;
    const int mg = wid >> 2;          // 0..3 -> rows mg*16..+15
    const int ng = wid & 3;           // 0..3 -> cols ng*32..+31
    const int cpair = 2 * (lane & 3);
    float* b1s = (float*)(smem + SM_B1);
    float* b2s = (float*)(smem + SM_B2);

    int tile = blockIdx.x;
    if (tile < NTILES) prefetch_z(sbase, zin, tile, tid);
    CP_COMMIT();

    // stage all 4 weight tiles once (pad 128->136 bf16 rows)
#pragma unroll
    for (int t = 0; t < 4; t++) {
        const uint4* src = (const uint4*)(wb + (size_t)t * 16384);
        char* dst = smem + t * WTILE_B;
        for (int i = tid; i < 2048; i += MLP_THREADS) {
            int r = i >> 4, c8 = i & 15;
            *(uint4*)(dst + r * TROW + c8 * 16) = src[i];
        }
    }
    if (tid < 128) { b1s[tid] = b1[tid]; b2s[tid] = b2[tid]; }
    __syncthreads();

    for (; tile < NTILES; tile += gridDim.x) {
        const int row0 = tile * 64;
        const int next = tile + gridDim.x;

        CP_WAIT0();
        __syncthreads();   // all threads' cp.async data visible

        // convert zraw -> A hi/lo tiles
        for (int i = tid; i < 4096; i += MLP_THREADS) {   // 64 rows x 64 col-pairs
            int r = i >> 6, cp = i & 63, col = cp * 2;
            float2 v = make_float2(0.f, 0.f);
            if (row0 + r < N_NODES)
                v = *(const float2*)(smem + SM_ZRAW + r * 512 + col * 4);
            __nv_bfloat16 h0 = __float2bfloat16_rn(v.x), h1 = __float2bfloat16_rn(v.y);
            *(unsigned*)(smem + SM_AHI + r * TROW + col * 2) = pack_bf16(h0, h1);
            *(unsigned*)(smem + SM_ALO + r * TROW + col * 2) =
                pack_bf16(__float2bfloat16_rn(v.x - __bfloat162float(h0)),
                          __float2bfloat16_rn(v.y - __bfloat162float(h1)));
        }
        __syncthreads();   // A ready; zraw free

        if (next < NTILES) prefetch_z(sbase, zin, next, tid);
        CP_COMMIT();

        float acc[4][4];

        // ---- GEMM1: t = relu(z @ W1^T + b1) ----
#pragma unroll
        for (int nt = 0; nt < 4; nt++) {
            int col = ng * 32 + (nt >> 1) * 16 + (nt & 1) * 8 + cpair;
            float bb0 = b1s[col], bb1 = b1s[col + 1];
            acc[nt][0] = bb0; acc[nt][1] = bb1;
            acc[nt][2] = bb0; acc[nt][3] = bb1;
        }
        gemm64(sbase, SM_W1HI, SM_W1LO, mg, ng, lane, acc);
        __syncthreads();   // all warps done reading A

        // epilogue1: relu + hi/lo re-split into A tiles
        {
            int rA = mg * 16 + (lane >> 2);
#pragma unroll
            for (int nt = 0; nt < 4; nt++) {
                int col = ng * 32 + (nt >> 1) * 16 + (nt & 1) * 8 + cpair;
                float v0 = fmaxf(acc[nt][0], 0.f), v1 = fmaxf(acc[nt][1], 0.f);
                float v2 = fmaxf(acc[nt][2], 0.f), v3 = fmaxf(acc[nt][3], 0.f);
                __nv_bfloat16 h0 = __float2bfloat16_rn(v0), h1 = __float2bfloat16_rn(v1);
                __nv_bfloat16 h2 = __float2bfloat16_rn(v2), h3 = __float2bfloat16_rn(v3);
                *(unsigned*)(smem + SM_AHI + rA * TROW + col * 2) = pack_bf16(h0, h1);
                *(unsigned*)(smem + SM_AHI + (rA + 8) * TROW + col * 2) = pack_bf16(h2, h3);
                *(unsigned*)(smem + SM_ALO + rA * TROW + col * 2) =
                    pack_bf16(__float2bfloat16_rn(v0 - __bfloat162float(h0)),
                              __float2bfloat16_rn(v1 - __bfloat162float(h1)));
                *(unsigned*)(smem + SM_ALO + (rA + 8) * TROW + col * 2) =
                    pack_bf16(__float2bfloat16_rn(v2 - __bfloat162float(h2)),
                              __float2bfloat16_rn(v3 - __bfloat162float(h3)));
            }
        }
        __syncthreads();

        // ---- GEMM2: out = relu(t @ W2^T + b2) ----
#pragma unroll
        for (int nt = 0; nt < 4; nt++) {
            int col = ng * 32 + (nt >> 1) * 16 + (nt & 1) * 8 + cpair;
            float bb0 = b2s[col], bb1 = b2s[col + 1];
            acc[nt][0] = bb0; acc[nt][1] = bb1;
            acc[nt][2] = bb0; acc[nt][3] = bb1;
        }
        gemm64(sbase, SM_W2HI, SM_W2LO, mg, ng, lane, acc);

        // epilogue2: relu + fp16 store (half2 pairs)
        {
            int grA = row0 + mg * 16 + (lane >> 2);
            int grB = grA + 8;
#pragma unroll
            for (int nt = 0; nt < 4; nt++) {
                int col = ng * 32 + (nt >> 1) * 16 + (nt & 1) * 8 + cpair;
                if (grA < N_NODES) {
                    __half2 hv = __floats2half2_rn(fmaxf(acc[nt][0], 0.f),
                                                   fmaxf(acc[nt][1], 0.f));
                    *(unsigned*)(hout + (size_t)grA * NHID + col) = *(unsigned*)&hv;
                }
                if (grB < N_NODES) {
                    __half2 hv = __floats2half2_rn(fmaxf(acc[nt][2], 0.f),
                                                   fmaxf(acc[nt][3], 0.f));
                    *(unsigned*)(hout + (size_t)grB * NHID + col) = *(unsigned*)&hv;
                }
            }
        }
        __syncthreads();   // A reads done before next convert overwrites
    }
}

// ---------------- pooling + log_softmax --------------------------------------
__global__ void pool_zero_kernel() {
    int i = blockIdx.x * blockDim.x + threadIdx.x;
    if (i < N_GRAPHS * NHID) g_pool[i] = 0.f;
}
__global__ void pool_kernel(const __half* __restrict__ h,
                            const void* __restrict__ batch_raw) {
    int t = blockIdx.x * blockDim.x + threadIdx.x;
    int n = t >> 5;
    int c = (t & 31) << 2;
    int g = load_idx(batch_raw, n, g_idx64);
    float4 v = make_float4(0.f, 0.f, 0.f, 0.f);
    acc_h4(v, h + (size_t)n * NHID + c);
    red_add_v4(g_pool + g * NHID + c, v);
}
__global__ void lsm_kernel(float* __restrict__ out) {
    int r = blockIdx.x;
    int c = threadIdx.x;
    int w = c >> 5, lane = c & 31;
    __shared__ float smax[4], ssum[4];
    float v = g_pool[r * NHID + c];
    float m = v;
#pragma unroll
    for (int off = 16; off > 0; off >>= 1)
        m = fmaxf(m, __shfl_xor_sync(0xffffffffu, m, off));
    if (lane == 0) smax[w] = m;
    __syncthreads();
    m = fmaxf(fmaxf(smax[0], smax[1]), fmaxf(smax[2], smax[3]));
    float e = expf(v - m);
    float s = e;
#pragma unroll
    for (int off = 16; off > 0; off >>= 1)
        s += __shfl_xor_sync(0xffffffffu, s, off);
    if (lane == 0) ssum[w] = s;
    __syncthreads();
    s = ssum[0] + ssum[1] + ssum[2] + ssum[3];
    out[r * NHID + c] = (v - m) - logf(s);
}

// ---------------- launch -----------------------------------------------------
extern "C" void kernel_launch(void* const* d_in, const int* in_sizes, int n_in,
                              void* d_out, int out_size) {
    const float* x     = nullptr;
    const void*  ei    = nullptr;
    const void*  batch = nullptr;
    const float *W1 = nullptr, *b1 = nullptr, *W2 = nullptr, *b2 = nullptr;
    for (int i = 0; i < n_in; i++) {
        int sz = in_sizes[i];
        if (sz == N_NODES * NHID)            x = (const float*)d_in[i];
        else if (sz == 2 * N_EDGES)          ei = d_in[i];
        else if (sz == N_NODES)              batch = d_in[i];
        else if (sz == NLAYER * NHID * NHID) { if (!W1) W1 = (const float*)d_in[i]; else W2 = (const float*)d_in[i]; }
        else if (sz == NLAYER * NHID)        { if (!b1) b1 = (const float*)d_in[i]; else b2 = (const float*)d_in[i]; }
    }
    float* out = (float*)d_out;

    float* zp = nullptr;
    __half* hp = nullptr;
    unsigned short* wb = nullptr;
    cudaGetSymbolAddress((void**)&zp, g_z);
    cudaGetSymbolAddress((void**)&hp, g_hh);
    cudaGetSymbolAddress((void**)&wb, g_wb);

    cudaFuncSetAttribute(mlp_mma_kernel, cudaFuncAttributeMaxDynamicSharedMemorySize, MMA_SMEM_BYTES);

    const int n4 = N_NODES * NHID / 4;
    const int scan_blocks = (N_NODES + 1023) / 1024;
    const int edge_blocks = (N_EDGES + 255) / 256;
    const int node_blocks = (N_NODES + 255) / 256;
    const int agg_blocks  = (N_NODES * 32 + 255) / 256;
    const int pool_blocks = (N_NODES * 32) / 256;

    detect_degzero_kernel<<<node_blocks, 256>>>((const int*)ei);
    x16_kernel<<<(n4 + 255) / 256, 256>>>((const float4*)x, n4);
    hist_kernel<<<edge_blocks, 256>>>(ei);
    scan1_kernel<<<scan_blocks, 1024>>>();
    scan2_kernel<<<1, 128>>>(scan_blocks);
    scan3_kernel<<<node_blocks, 256>>>();
    fill_kernel<<<edge_blocks, 256>>>(ei);
    wconv_kernel<<<6, 256>>>(W1, W2);

    for (int l = 0; l < NLAYER; l++) {
        gin_agg_kernel<<<agg_blocks, 256>>>(hp, zp);
        mlp_mma_kernel<<<148, MLP_THREADS, MMA_SMEM_BYTES>>>(
            zp, wb + (size_t)l * 4 * 16384, b1 + l * NHID, b2 + l * NHID, hp);
    }

    pool_zero_kernel<<<(N_GRAPHS * NHID + 255) / 256, 256>>>();
    pool_kernel<<<pool_blocks, 256>>>(hp, batch);
    lsm_kernel<<<N_GRAPHS, NHID>>>(out);
}